// round 8
// baseline (speedup 1.0000x reference)
#include <cuda_runtime.h>
#include <cstdint>

#define T_STEPS 100
#define BATCH   256
#define IN_DIM  1024
#define HID     2048
#define OUT_DIM 10
#define BH      (BATCH * HID)
#define TBROWS  (T_STEPS * BATCH)
#define XL_MAX  512

// ---------------- scratch (device globals; no runtime allocation) ----------------
__device__ __align__(128) int8_t   g_X[(size_t)TBROWS * IN_DIM];
__device__ __align__(128) uint16_t g_xlist[(size_t)TBROWS * XL_MAX];
__device__ __align__(128) int      g_xlen[TBROWS];
__device__ __align__(128) float    g_I0[(size_t)TBROWS * HID];
__device__ __align__(128) float    g_I1[BH];
__device__ __align__(128) float    g_v0[BH];
__device__ __align__(128) float    g_v1[BH];
__device__ __align__(128) float    g_vout[BATCH * OUT_DIM];
__device__ __align__(128) float    g_cnt[BATCH * OUT_DIM];
__device__ __align__(128) uint16_t g_s0list[BATCH * HID];
__device__ __align__(128) int      g_s0len[BATCH];
__device__ __align__(128) uint16_t g_s1list[BATCH * HID];
__device__ __align__(128) int      g_s1len[BATCH];

// first index in ascending smem list with value >= bound
__device__ __forceinline__ int lbound(const uint16_t* sl, int len, int bound) {
    int lo = 0, hi = len;
    while (lo < hi) { const int mid = (lo + hi) >> 1; if (sl[mid] < bound) lo = mid + 1; else hi = mid; }
    return lo;
}

// ---------------- prep ----------------
__global__ void prep_x_k(const float* __restrict__ in0) {
    __shared__ float tile[32][33];
    const int b  = blockIdx.z;
    const int i0 = blockIdx.x * 32;
    const int t0 = blockIdx.y * 32;
    const int tx = threadIdx.x, ty = threadIdx.y;
    if (t0 + tx < T_STEPS)
        tile[ty][tx] = in0[((size_t)b * IN_DIM + (i0 + ty)) * T_STEPS + t0 + tx];
    __syncthreads();
    const int t = t0 + ty;
    if (t < T_STEPS)
        g_X[((size_t)t * BATCH + b) * IN_DIM + i0 + tx] = (tile[tx][ty] > 0.5f) ? 1 : 0;
}

__global__ void build_xlist_k() {
    const int row  = blockIdx.x * (blockDim.x >> 5) + (threadIdx.x >> 5);
    const int lane = threadIdx.x & 31;
    if (row >= TBROWS) return;
    const int8_t* x = g_X + (size_t)row * IN_DIM;
    uint16_t* lst = g_xlist + (size_t)row * XL_MAX;
    int base = 0;
#pragma unroll 4
    for (int c = 0; c < IN_DIM / 32; c++) {
        const int k = c * 32 + lane;
        const bool sp = x[k] != 0;
        const unsigned m = __ballot_sync(0xffffffffu, sp);
        const int pos = __popc(m & ((1u << lane) - 1u));
        if (sp && base + pos < XL_MAX) lst[base + pos] = (uint16_t)k;
        base += __popc(m);
    }
    if (lane == 0) g_xlen[row] = base < XL_MAX ? base : XL_MAX;
}

__global__ void init_k() {
    const int i = blockIdx.x * blockDim.x + threadIdx.x;
    if (i < BH) { g_v0[i] = 0.f; g_v1[i] = 0.f; }
    if (i < BATCH * OUT_DIM) g_vout[i] = 0.f;
}

// ---------------- phase A: chunked-serial (S=4, chunk=256) layer-0 currents ----------------
__global__ void __launch_bounds__(512) phaseA_k(const float* __restrict__ W) {
    __shared__ uint16_t sl[XL_MAX];
    const int row = blockIdx.x;
    const int len = g_xlen[row];
    for (int i = threadIdx.x; i < len; i += 512) sl[i] = g_xlist[(size_t)row * XL_MAX + i];
    __syncthreads();
    int bnd[5];
    bnd[0] = 0; bnd[4] = len;
    bnd[1] = lbound(sl, len, 256); bnd[2] = lbound(sl, len, 512); bnd[3] = lbound(sl, len, 768);
    const int n = threadIdx.x * 4;
    float s[4][4];
#pragma unroll
    for (int c = 0; c < 4; c++) { s[c][0] = s[c][1] = s[c][2] = s[c][3] = 0.f; }
#pragma unroll
    for (int c = 0; c < 4; c++) {
        for (int i = bnd[c]; i < bnd[c + 1]; i++) {
            const float4 w = *(const float4*)(W + (size_t)sl[i] * HID + n);
            s[c][0] = __fadd_rn(s[c][0], w.x); s[c][1] = __fadd_rn(s[c][1], w.y);
            s[c][2] = __fadd_rn(s[c][2], w.z); s[c][3] = __fadd_rn(s[c][3], w.w);
        }
    }
    float r[4];
#pragma unroll
    for (int j = 0; j < 4; j++)
        r[j] = __fadd_rn(__fadd_rn(__fadd_rn(s[0][j], s[1][j]), s[2][j]), s[3][j]);
    *(float4*)(g_I0 + (size_t)row * HID + n) = make_float4(r[0], r[1], r[2], r[3]);
}

// ---------------- per-step: LIF + ascending list build (CTA per batch row) ----------------
__global__ void __launch_bounds__(256) liflist_k(const float* __restrict__ I,
                                                 float* __restrict__ v,
                                                 uint16_t* __restrict__ lst,
                                                 int* __restrict__ len) {
    __shared__ uint8_t fl[HID];
    __shared__ int wpre[9];
    const int b = blockIdx.x;
    const float* Ib = I + (size_t)b * HID;
    float* vb = v + (size_t)b * HID;
#pragma unroll
    for (int j = 0; j < 8; j++) {
        const int n = j * 256 + threadIdx.x;
        const float vv = __fadd_rn(__fmul_rn(vb[n], 0.9f), Ib[n]);
        const bool sp = vv >= 1.0f;
        vb[n] = sp ? 0.f : vv;
        fl[n] = sp ? 1 : 0;
    }
    __syncthreads();
    const int wid = threadIdx.x >> 5, lane = threadIdx.x & 31;
    int cnt = 0;
#pragma unroll
    for (int c = 0; c < 8; c++)
        cnt += __popc(__ballot_sync(0xffffffffu, fl[wid * 256 + c * 32 + lane] != 0));
    if (lane == 0) wpre[wid] = cnt;
    __syncthreads();
    if (threadIdx.x == 0) {
        int s = 0;
#pragma unroll
        for (int w = 0; w < 8; w++) { const int c = wpre[w]; wpre[w] = s; s += c; }
        wpre[8] = s;
    }
    __syncthreads();
    int base = wpre[wid];
#pragma unroll
    for (int c = 0; c < 8; c++) {
        const int n = wid * 256 + c * 32 + lane;
        const bool sp = fl[n] != 0;
        const unsigned m = __ballot_sync(0xffffffffu, sp);
        const int pos = __popc(m & ((1u << lane) - 1u));
        if (sp) lst[b * HID + base + pos] = (uint16_t)n;
        base += __popc(m);
    }
    if (threadIdx.x == 0) len[b] = wpre[8];
}

// ---------------- per-step hidden: chunked-serial (S=4, chunk=512) ----------------
__global__ void __launch_bounds__(256) hidden_k(const float* __restrict__ W) {
    __shared__ uint16_t sl[HID];
    __shared__ int sb[3];
    const int b = blockIdx.x >> 1, half = blockIdx.x & 1;
    const int len = g_s0len[b];
    for (int i = threadIdx.x; i < len; i += 256) sl[i] = g_s0list[b * HID + i];
    __syncthreads();
    if (threadIdx.x < 3) sb[threadIdx.x] = lbound(sl, len, (threadIdx.x + 1) * 512);
    __syncthreads();
    int bnd[5];
    bnd[0] = 0; bnd[1] = sb[0]; bnd[2] = sb[1]; bnd[3] = sb[2]; bnd[4] = len;
    const int n = half * 1024 + threadIdx.x * 4;
    float s[4][4];
#pragma unroll
    for (int c = 0; c < 4; c++) { s[c][0] = s[c][1] = s[c][2] = s[c][3] = 0.f; }
#pragma unroll
    for (int c = 0; c < 4; c++) {
        for (int i = bnd[c]; i < bnd[c + 1]; i++) {
            const float4 w = *(const float4*)(W + (size_t)sl[i] * HID + n);
            s[c][0] = __fadd_rn(s[c][0], w.x); s[c][1] = __fadd_rn(s[c][1], w.y);
            s[c][2] = __fadd_rn(s[c][2], w.z); s[c][3] = __fadd_rn(s[c][3], w.w);
        }
    }
    float r[4];
#pragma unroll
    for (int j = 0; j < 4; j++)
        r[j] = __fadd_rn(__fadd_rn(__fadd_rn(s[0][j], s[1][j]), s[2][j]), s[3][j]);
    *(float4*)(g_I1 + (size_t)b * HID + n) = make_float4(r[0], r[1], r[2], r[3]);
}

// ---------------- per-step output: EXACT (fp64) gather + LIF out + rate (order-insensitive) ----------------
__global__ void __launch_bounds__(256) outstep_k(const float* __restrict__ Who, int t,
                                                 float* __restrict__ d_out) {
    const int b = blockIdx.x * 8 + (threadIdx.x >> 5);
    const int lane = threadIdx.x & 31;
    const int len = g_s1len[b];
    const uint16_t* __restrict__ lst = g_s1list + b * HID;
    if (lane < OUT_DIM) {
        double acc = 0.0;
        for (int i = 0; i < len; i++) {
            const int k = lst[i];
            acc += (double)__ldg(Who + k * OUT_DIM + lane);
        }
        const int o = b * OUT_DIM + lane;
        const float vo = __fadd_rn(__fmul_rn(g_vout[o], 0.9f), (float)acc);
        const bool sp = vo >= 1.0f;
        g_vout[o] = sp ? 0.f : vo;
        const float c = (t == 0 ? 0.f : g_cnt[o]) + (sp ? 1.f : 0.f);
        if (t == T_STEPS - 1) d_out[o] = c / 100.0f;
        else g_cnt[o] = c;
    }
}

// ---------------- launch ----------------
extern "C" void kernel_launch(void* const* d_in, const int* in_sizes, int n_in,
                              void* d_out, int out_size) {
    (void)in_sizes; (void)n_in; (void)out_size;
    const float* in_bins = (const float*)d_in[0];
    const float* W_ih    = (const float*)d_in[1];
    const float* W_hh    = (const float*)d_in[2];
    const float* W_ho    = (const float*)d_in[3];
    float* out = (float*)d_out;

    void *pI0, *pI1, *pv0, *pv1, *ps0l, *ps0n, *ps1l, *ps1n;
    cudaGetSymbolAddress(&pI0, g_I0);
    cudaGetSymbolAddress(&pI1, g_I1);
    cudaGetSymbolAddress(&pv0, g_v0);
    cudaGetSymbolAddress(&pv1, g_v1);
    cudaGetSymbolAddress(&ps0l, g_s0list);
    cudaGetSymbolAddress(&ps0n, g_s0len);
    cudaGetSymbolAddress(&ps1l, g_s1list);
    cudaGetSymbolAddress(&ps1n, g_s1len);

    init_k<<<2048, 256>>>();
    prep_x_k<<<dim3(IN_DIM / 32, 4, BATCH), dim3(32, 32)>>>(in_bins);
    build_xlist_k<<<(TBROWS + 7) / 8, 256>>>();

    phaseA_k<<<TBROWS, 512>>>(W_ih);

    for (int t = 0; t < T_STEPS; t++) {
        liflist_k<<<BATCH, 256>>>((const float*)pI0 + (size_t)t * BH, (float*)pv0,
                                  (uint16_t*)ps0l, (int*)ps0n);
        hidden_k<<<BATCH * 2, 256>>>(W_hh);
        liflist_k<<<BATCH, 256>>>((const float*)pI1, (float*)pv1,
                                  (uint16_t*)ps1l, (int*)ps1n);
        outstep_k<<<BATCH / 8, 256>>>(W_ho, t, out);
    }
}